// round 1
// baseline (speedup 1.0000x reference)
#include <cuda_runtime.h>

#define HH 4
#define BB 1024
#define LL 200
#define DQv 512
#define DFv 128
#define DD1 128
#define DD2 64

// Collapsed weights (static device scratch — allowed)
__device__ float g_Wq[HH * DQv * DD2];   // [h][k][c]
__device__ float g_bq[HH * DD2];
__device__ float g_Wc[HH * DFv * 128];   // [h][k][c]  c<64: f-path, c>=64: v-path
__device__ float g_bc[HH * 128];

// ---------------- packed f32x2 helpers ----------------
__device__ __forceinline__ unsigned long long dup2(float x) {
    unsigned long long r;
    unsigned int u = __float_as_uint(x);
    asm("mov.b64 %0, {%1, %1};" : "=l"(r) : "r"(u));
    return r;
}
__device__ __forceinline__ void ffma2(unsigned long long& d, unsigned long long a, unsigned long long b) {
    asm("fma.rn.f32x2 %0, %1, %2, %0;" : "+l"(d) : "l"(a), "l"(b));
}
__device__ __forceinline__ float2 unpk(unsigned long long v) {
    unsigned int lo, hi;
    asm("mov.b64 {%0, %1}, %2;" : "=r"(lo), "=r"(hi) : "l"(v));
    return make_float2(__uint_as_float(lo), __uint_as_float(hi));
}
__device__ __forceinline__ float silu_f(float x) {
    return x / (1.f + __expf(-x));
}

// ---------------- weight collapse kernels ----------------
__global__ void collapse_q_kernel(const float* __restrict__ Wq1, const float* __restrict__ bq1,
                                  const float* __restrict__ Wq2, const float* __restrict__ bq2) {
    int idx = blockIdx.x * 256 + threadIdx.x;      // < 4*512*64 = 131072
    int c = idx & 63;
    int k = (idx >> 6) & 511;
    int h = idx >> 15;
    const float* a  = Wq1 + (h * DQv + k) * DD1;
    const float* w2 = Wq2 + h * DD1 * DD2 + c;
    float acc = 0.f;
#pragma unroll 8
    for (int j = 0; j < DD1; ++j) acc += a[j] * w2[j * DD2];
    g_Wq[idx] = acc;
    if (k == 0) {
        float bb = bq2[h * DD2 + c];
        const float* b1p = bq1 + h * DD1;
#pragma unroll 8
        for (int j = 0; j < DD1; ++j) bb += b1p[j] * w2[j * DD2];
        g_bq[h * DD2 + c] = bb;
    }
}

__global__ void collapse_fv_kernel(const float* __restrict__ Wf1, const float* __restrict__ bf1,
                                   const float* __restrict__ Wf2, const float* __restrict__ bf2,
                                   const float* __restrict__ Wv1, const float* __restrict__ bv1,
                                   const float* __restrict__ Wv2, const float* __restrict__ bv2) {
    int idx = blockIdx.x * 256 + threadIdx.x;      // < 4*128*128 = 65536
    int c = idx & 127;
    int k = (idx >> 7) & 127;
    int h = idx >> 14;
    const float *W1, *W2, *B1, *B2;
    int cc;
    if (c < 64) { W1 = Wf1; W2 = Wf2; B1 = bf1; B2 = bf2; cc = c; }
    else        { W1 = Wv1; W2 = Wv2; B1 = bv1; B2 = bv2; cc = c - 64; }
    const float* a  = W1 + (h * DFv + k) * DD1;
    const float* w2 = W2 + h * DD1 * DD2 + cc;
    float acc = 0.f;
#pragma unroll 8
    for (int j = 0; j < DD1; ++j) acc += a[j] * w2[j * DD2];
    g_Wc[idx] = acc;
    if (k == 0) {
        float bb = B2[h * DD2 + cc];
        const float* b1p = B1 + h * DD1;
#pragma unroll 8
        for (int j = 0; j < DD1; ++j) bb += b1p[j] * w2[j * DD2];
        g_bc[h * 128 + c] = bb;
    }
}

// ---------------- fused main kernel: one block per (b,h) ----------------
// smem (floats): W_s 16384 | fact_s 5120 | fv_s 12800 | logits 208 | fq 64 | bc 128 | red 256 | misc 32
#define SMEM_FLOATS (16384 + 5120 + 12800 + 208 + 64 + 128 + 256 + 32)
#define SMEM_BYTES  (SMEM_FLOATS * 4)

__global__ __launch_bounds__(256, 1) void mha_main_kernel(
    const float* __restrict__ query, const float* __restrict__ fact,
    const int* __restrict__ mask, const float* __restrict__ mm,
    const float* __restrict__ tau1, const float* __restrict__ tau2,
    float* __restrict__ out)
{
    extern __shared__ float sm[];
    float* W_s      = sm;                 // [128][128]
    float* fact_s   = W_s + 16384;        // [40][128]
    float* fv_s     = fact_s + 5120;      // [200][64]
    float* logits_s = fv_s + 12800;       // [200] (+pad)
    float* fq_s     = logits_s + 208;     // [64]
    float* bc_s     = fq_s + 64;          // [128]
    float* red_s    = bc_s + 128;         // [256]
    float* misc     = red_s + 256;        // [32]

    const int tid = threadIdx.x;
    const int b = blockIdx.x >> 2;
    const int h = blockIdx.x & 3;
    const int rg = tid >> 5;              // warp id (l-group)
    const int c4 = tid & 31;              // column quad

    // stage combined weights into smem
    {
        const float4* gw = reinterpret_cast<const float4*>(g_Wc + h * 16384);
        float4* ws4 = reinterpret_cast<float4*>(W_s);
#pragma unroll
        for (int i = 0; i < 16; ++i) ws4[tid + 256 * i] = gw[tid + 256 * i];
    }
    if (tid < 128) bc_s[tid] = g_bc[h * 128 + tid];

    // fq = silu(query @ Wq_eff + bq_eff), split-K over 4 groups of 64 threads
    {
        int c = tid & 63, part = tid >> 6;
        const float* q  = query + b * DQv + part * 128;
        const float* wq = g_Wq + h * DQv * DD2 + part * 128 * DD2 + c;
        float acc = 0.f;
#pragma unroll 8
        for (int k = 0; k < 128; ++k) acc += q[k] * wq[k * DD2];
        red_s[tid] = acc;
    }
    __syncthreads();
    if (tid < 64) {
        float z = red_s[tid] + red_s[64 + tid] + red_s[128 + tid] + red_s[192 + tid]
                + g_bq[h * 64 + tid];
        fq_s[tid] = silu_f(z);
    }
    __syncthreads();

    const float t1a = tau1[h], t1b = tau1[4 + h];
    const float cb1 = tau2[h], cb2 = tau2[4 + h], cb3 = tau2[8 + h];

    float bcv[4], fqv[4];
#pragma unroll
    for (int j = 0; j < 4; ++j) bcv[j] = bc_s[c4 * 4 + j];
    if (c4 < 16) {
#pragma unroll
        for (int j = 0; j < 4; ++j) fqv[j] = fq_s[c4 * 4 + j];
    } else {
#pragma unroll
        for (int j = 0; j < 4; ++j) fqv[j] = 0.f;
    }

    const int lbase = rg * 5;   // 5 rows per thread within a 40-row tile

    for (int t = 0; t < 5; ++t) {
        const int tb = t * 40;
        __syncthreads();        // protect fact_s rewrite against previous tile reads
        {
            const int lane = c4;
#pragma unroll
            for (int j = 0; j < 5; ++j) {
                int lrow = rg + 8 * j;   // 0..39
                const float4* src = reinterpret_cast<const float4*>(fact + (b * 200 + tb + lrow) * 128);
                reinterpret_cast<float4*>(fact_s + lrow * 128)[lane] = src[lane];
            }
        }
        __syncthreads();

        unsigned long long acc0[5], acc1[5];
#pragma unroll
        for (int i = 0; i < 5; ++i) { acc0[i] = 0ull; acc1[i] = 0ull; }

#pragma unroll 8
        for (int k4 = 0; k4 < 32; ++k4) {
            ulonglong2 w0 = *reinterpret_cast<const ulonglong2*>(W_s + (k4 * 4 + 0) * 128 + c4 * 4);
            ulonglong2 w1 = *reinterpret_cast<const ulonglong2*>(W_s + (k4 * 4 + 1) * 128 + c4 * 4);
            ulonglong2 w2 = *reinterpret_cast<const ulonglong2*>(W_s + (k4 * 4 + 2) * 128 + c4 * 4);
            ulonglong2 w3 = *reinterpret_cast<const ulonglong2*>(W_s + (k4 * 4 + 3) * 128 + c4 * 4);
#pragma unroll
            for (int i = 0; i < 5; ++i) {
                float4 f = *reinterpret_cast<const float4*>(fact_s + (lbase + i) * 128 + k4 * 4);
                unsigned long long p;
                p = dup2(f.x); ffma2(acc0[i], p, w0.x); ffma2(acc1[i], p, w0.y);
                p = dup2(f.y); ffma2(acc0[i], p, w1.x); ffma2(acc1[i], p, w1.y);
                p = dup2(f.z); ffma2(acc0[i], p, w2.x); ffma2(acc1[i], p, w2.y);
                p = dup2(f.w); ffma2(acc0[i], p, w3.x); ffma2(acc1[i], p, w3.y);
            }
        }

        // epilogue: bias + silu; f-lanes form dot partials, v-lanes stash fv
        float pdot[5];
#pragma unroll
        for (int i = 0; i < 5; ++i) {
            float2 a0 = unpk(acc0[i]);
            float2 a1 = unpk(acc1[i]);
            float s0 = silu_f(a0.x + bcv[0]);
            float s1 = silu_f(a0.y + bcv[1]);
            float s2 = silu_f(a1.x + bcv[2]);
            float s3 = silu_f(a1.y + bcv[3]);
            if (c4 < 16) {
                pdot[i] = s0 * fqv[0] + s1 * fqv[1] + s2 * fqv[2] + s3 * fqv[3];
            } else {
                float4 vv = make_float4(s0, s1, s2, s3);
                *reinterpret_cast<float4*>(fv_s + (tb + lbase + i) * 64 + (c4 - 16) * 4) = vv;
                pdot[i] = 0.f;
            }
        }
        if (c4 < 16) {
#pragma unroll
            for (int i = 0; i < 5; ++i) {
#pragma unroll
                for (int off = 8; off > 0; off >>= 1)
                    pdot[i] += __shfl_xor_sync(0x0000ffffu, pdot[i], off);
            }
            if (c4 < 5) {
                float d0 = pdot[0];
                if (c4 == 1) d0 = pdot[1];
                else if (c4 == 2) d0 = pdot[2];
                else if (c4 == 3) d0 = pdot[3];
                else if (c4 == 4) d0 = pdot[4];
                int l = tb + lbase + c4;
                float mk = (float)mask[b * 200 + l];
                float dd = d0 + (-1e9f) * (1.f - mk);       // mask BEFORE cosine mixing (matches ref)
                float bias = mm[b * 200 + l] / t1a + mm[204800 + b * 200 + l] / t1b;
                logits_s[l] = cb1 * dd + cb2 * bias + cb3 * dd * bias;
            }
        }
    }
    __syncthreads();

    // ---- softmax over L=200 ----
    float v = (tid < 200) ? logits_s[tid] : -3.0e38f;
    float mxv = v;
#pragma unroll
    for (int off = 16; off > 0; off >>= 1)
        mxv = fmaxf(mxv, __shfl_xor_sync(0xffffffffu, mxv, off));
    if (c4 == 0) misc[rg] = mxv;
    __syncthreads();
    if (tid == 0) {
        float m = misc[0];
#pragma unroll
        for (int i = 1; i < 8; ++i) m = fmaxf(m, misc[i]);
        misc[8] = m;
    }
    __syncthreads();
    const float MX = misc[8];
    float e = (tid < 200) ? expf(v - MX) : 0.f;
    float se = e;
#pragma unroll
    for (int off = 16; off > 0; off >>= 1)
        se += __shfl_xor_sync(0xffffffffu, se, off);
    if (c4 == 0) misc[16 + rg] = se;
    __syncthreads();
    if (tid == 0) {
        float s = 0.f;
#pragma unroll
        for (int i = 0; i < 8; ++i) s += misc[16 + i];
        misc[9] = 1.f / s;
    }
    __syncthreads();
    const float invS = misc[9];
    if (tid < 200) logits_s[tid] = e * invS + 1e-7f;   // alphas + 1e-7 (applies to ALL l)
    __syncthreads();

    // ---- out[c] = sum_l fv[l][c] * w[l] ----
    {
        int c = tid & 63, lg = tid >> 6;
        float o = 0.f;
        for (int l = lg; l < 200; l += 4)
            o += fv_s[l * 64 + c] * logits_s[l];
        red_s[tid] = o;
    }
    __syncthreads();
    if (tid < 64) {
        float r = red_s[tid] + red_s[64 + tid] + red_s[128 + tid] + red_s[192 + tid];
        out[b * 256 + h * 64 + tid] = r;
    }
}

extern "C" void kernel_launch(void* const* d_in, const int* in_sizes, int n_in,
                              void* d_out, int out_size) {
    const float* query = (const float*)d_in[0];
    const float* fact  = (const float*)d_in[1];
    const int*   mask  = (const int*)  d_in[2];
    const float* mm    = (const float*)d_in[3];
    const float* Wq1   = (const float*)d_in[4];
    const float* bq1   = (const float*)d_in[5];
    const float* Wq2   = (const float*)d_in[6];
    const float* bq2   = (const float*)d_in[7];
    const float* Wf1   = (const float*)d_in[8];
    const float* bf1   = (const float*)d_in[9];
    const float* Wf2   = (const float*)d_in[10];
    const float* bf2   = (const float*)d_in[11];
    const float* Wv1   = (const float*)d_in[12];
    const float* bv1   = (const float*)d_in[13];
    const float* Wv2   = (const float*)d_in[14];
    const float* bv2   = (const float*)d_in[15];
    const float* tau1  = (const float*)d_in[16];
    const float* tau2  = (const float*)d_in[17];
    float* out = (float*)d_out;

    cudaFuncSetAttribute(mha_main_kernel, cudaFuncAttributeMaxDynamicSharedMemorySize, SMEM_BYTES);

    collapse_q_kernel<<<512, 256>>>(Wq1, bq1, Wq2, bq2);
    collapse_fv_kernel<<<256, 256>>>(Wf1, bf1, Wf2, bf2, Wv1, bv1, Wv2, bv2);
    mha_main_kernel<<<BB * HH, 256, SMEM_BYTES>>>(query, fact, mask, mm, tau1, tau2, out);
}